// round 6
// baseline (speedup 1.0000x reference)
#include <cuda_runtime.h>
#include <cuda_fp16.h>
#include <math.h>

#define BB 8
#define CC 16
#define PAIRS (CC/2)
#define HH 240
#define WW 320
#define NN (HH*WW)
#define ITER_BLOCKS (NN/256*BB)     // 300*8 = 2400

// ---------------- device-global state (no allocations allowed) ----------------
__device__ float g_R[BB][9];
__device__ float g_t[BB][3];
__device__ float g_acc[BB][27];          // 21 upper-tri JtWJ + 6 Rhs
__device__ unsigned int g_count;         // last-block counter (zero at load; reset after use)
// channel-pair layouts, plane-major over (b,pair):
//   g_cen2 : per (b,pair,p): uint4 {ag_c0, xs_c0, ag_c1, xs_c1}  (16B, ag=h2(a,g), xs=h2(x0,s0^2))
//   g_gath2: per (b,pair,p): uint2 {h2(x1,s1)_c0, h2(x1,s1)_c1}  (8B)
__device__ uint4 g_cen2[BB*PAIRS*NN];
__device__ uint2 g_gath2[BB*PAIRS*NN];

__device__ __forceinline__ unsigned pack_h2(float a, float b) {
    __half2 h = __floats2half2_rn(a, b);
    return *(unsigned*)&h;
}
__device__ __forceinline__ __half2 as_h2(unsigned u) { return *(__half2*)&u; }

__device__ __forceinline__ void rodrigues(float wx, float wy, float wz, float* R) {
    float th = sqrtf(wx*wx + wy*wy + wz*wz) + 1e-12f;
    float inv = 1.0f / th;
    float ax = wx*inv, ay = wy*inv, az = wz*inv;
    float s = sinf(th), c = cosf(th), mc = 1.0f - c;
    R[0] = c + mc*ax*ax;     R[1] = mc*ax*ay - s*az;  R[2] = mc*ax*az + s*ay;
    R[3] = mc*ax*ay + s*az;  R[4] = c + mc*ay*ay;     R[5] = mc*ay*az - s*ax;
    R[6] = mc*ax*az - s*ay;  R[7] = mc*ay*az + s*ax;  R[8] = c + mc*az*az;
}

// ---------------- pack: sobel + fp16 pack to channel-pair layout; init fused ----------------
__global__ __launch_bounds__(256)
void packKernel(const float* __restrict__ twist0, const float* __restrict__ x0,
                const float* __restrict__ sigma0, const float* __restrict__ x1,
                const float* __restrict__ sigma1) {
    if (blockIdx.x == 0 && threadIdx.x < BB) {      // fused init
        int b = threadIdx.x;
        rodrigues(twist0[b*6+0], twist0[b*6+1], twist0[b*6+2], g_R[b]);
        g_t[b][0] = twist0[b*6+3];
        g_t[b][1] = twist0[b*6+4];
        g_t[b][2] = twist0[b*6+5];
#pragma unroll
        for (int k = 0; k < 27; k++) g_acc[b][k] = 0.0f;
    }

    int t = blockIdx.x * 256 + threadIdx.x;         // one thread = 1 pixel, one channel-pair
    int p  = t % NN;
    int bp = t / NN;
    int b    = bp >> 3;
    int pair = bp & 7;
    int v = p / WW, u = p - v*WW;

    int vm = max(v-1, 0)*WW, v0 = v*WW, vp = min(v+1, HH-1)*WW;
    int um = max(u-1, 0), up = min(u+1, WW-1);

    unsigned agx[2], xsx[2], ggx[2];
#pragma unroll
    for (int ch = 0; ch < 2; ch++) {
        int c = pair*2 + ch;
        size_t off = (size_t)(b*CC + c)*NN;
        const float* img = x0 + off;
        float tl = img[vm+um], tc_ = img[vm+u], tr = img[vm+up];
        float ml = img[v0+um], mc_ = img[v0+u], mr = img[v0+up];
        float bl = img[vp+um], bc_ = img[vp+u], br = img[vp+up];
        float dx = tr - tl + 2.0f*(mr - ml) + (br - bl);
        float dy = bl - tl + 2.0f*(bc_ - tc_) + (br - tr);
        float rinv = rsqrtf(dx*dx + dy*dy + 1e-8f);
        float s0 = sigma0[off + p];
        agx[ch] = pack_h2(dx*rinv, dy*rinv);
        xsx[ch] = pack_h2(mc_, s0*s0);
        ggx[ch] = pack_h2(x1[off + p], sigma1[off + p]);
    }
    g_cen2[t]  = make_uint4(agx[0], xsx[0], agx[1], xsx[1]);
    g_gath2[t] = make_uint2(ggx[0], ggx[1]);
}

// ---------------- fused per-iteration accumulation + last-block solve (1 px/thread) ----------------
__global__ __launch_bounds__(256)
void iterKernel(const float* __restrict__ invD0, const float* __restrict__ invD1,
                const float* __restrict__ Kmat, float* __restrict__ out, int last)
{
    const int b = blockIdx.y;
    const int p = blockIdx.x * 256 + threadIdx.x;

    float acc[27];
#pragma unroll
    for (int k = 0; k < 27; k++) acc[k] = 0.0f;

    {
        const float fx = Kmat[b*4+0], fy = Kmat[b*4+1];
        const float cx = Kmat[b*4+2], cy = Kmat[b*4+3];
        const float ifx = 1.0f/fx, ify = 1.0f/fy;
        const float* Rb = g_R[b];
        const float* tb = g_t[b];

        int vpix = p / WW;
        int upix = p - vpix*WW;
        float y = ((float)vpix - cy) * ify;
        float x = ((float)upix - cx) * ifx;
        float d = invD0[(size_t)b*NN + p];

        float X = Rb[0]*x + Rb[1]*y + Rb[2] + tb[0]*d;
        float Y = Rb[3]*x + Rb[4]*y + Rb[5] + tb[1]*d;
        float S = Rb[6]*x + Rb[7]*y + Rb[8] + tb[2]*d;
        float invS = __fdividef(1.0f, S);
        float u = X * invS * fx + cx;
        float v = Y * invS * fy + cy;
        float invz = d * invS;

        float uc = fminf(fmaxf(u, 0.0f), (float)(WW-1));
        float vc = fminf(fmaxf(v, 0.0f), (float)(HH-1));
        float x0f = floorf(uc), y0f = floorf(vc);
        float wx = uc - x0f, wy = vc - y0f;
        int xi0 = (int)x0f, yi0 = (int)y0f;
        int xi1 = min(xi0 + 1, WW-1), yi1 = min(yi0 + 1, HH-1);
        float w00 = (1.0f-wx)*(1.0f-wy), w01 = wx*(1.0f-wy);
        float w10 = (1.0f-wx)*wy,        w11 = wx*wy;
        int o00 = yi0*WW + xi0, o01 = yi0*WW + xi1;
        int o10 = yi1*WW + xi0, o11 = yi1*WW + xi1;
        __half2 W00 = __float2half2_rn(w00), W01 = __float2half2_rn(w01);
        __half2 W10 = __float2half2_rn(w10), W11 = __float2half2_rn(w11);

        const float* D1 = invD1 + (size_t)b*NN;
        float dz = D1[o00]*w00 + D1[o01]*w01 + D1[o10]*w10 + D1[o11]*w11;
        bool inlier = invz > dz - 0.1f;
        bool inview = (u > 0.0f) && (u < (float)WW) && (v > 0.0f) && (v < (float)HH);
        float valid = (inlier && inview) ? 1.0f : 0.0f;

        float Saa = 0.0f, Sab = 0.0f, Sbb = 0.0f, Sar = 0.0f, Sbr = 0.0f;
#pragma unroll
        for (int pair = 0; pair < PAIRS; pair++) {
            size_t plane = (size_t)(b*PAIRS + pair)*NN;
            uint4 cv = __ldg(&g_cen2[plane + p]);
            const uint2* G = g_gath2 + plane;
            uint2 q00 = __ldg(G + o00);
            uint2 q01 = __ldg(G + o01);
            uint2 q10 = __ldg(G + o10);
            uint2 q11 = __ldg(G + o11);

            __half2 fs0 = __hmul2(as_h2(q00.x), W00);
            fs0 = __hfma2(as_h2(q01.x), W01, fs0);
            fs0 = __hfma2(as_h2(q10.x), W10, fs0);
            fs0 = __hfma2(as_h2(q11.x), W11, fs0);
            __half2 fs1 = __hmul2(as_h2(q00.y), W00);
            fs1 = __hfma2(as_h2(q01.y), W01, fs1);
            fs1 = __hfma2(as_h2(q10.y), W10, fs1);
            fs1 = __hfma2(as_h2(q11.y), W11, fs1);

            {
                float2 frsr = __half22float2(fs0);
                float2 ag   = __half22float2(as_h2(cv.x));
                float2 xss  = __half22float2(as_h2(cv.y));
                float s2  = frsr.y*frsr.y + xss.y;
                float wgt = __fdividef(1.0f, s2);
                float res = frsr.x - xss.x;
                float aw = ag.x*wgt, gw = ag.y*wgt;
                Saa += aw*ag.x;  Sab += aw*ag.y;  Sbb += gw*ag.y;
                Sar += aw*res;   Sbr += gw*res;
            }
            {
                float2 frsr = __half22float2(fs1);
                float2 ag   = __half22float2(as_h2(cv.z));
                float2 xss  = __half22float2(as_h2(cv.w));
                float s2  = frsr.y*frsr.y + xss.y;
                float wgt = __fdividef(1.0f, s2);
                float res = frsr.x - xss.x;
                float aw = ag.x*wgt, gw = ag.y*wgt;
                Saa += aw*ag.x;  Sab += aw*ag.y;  Sbb += gw*ag.y;
                Sar += aw*res;   Sbr += gw*res;
            }
        }

        // expand the pixel's S into 27 accumulators
        Saa *= valid; Sab *= valid; Sbb *= valid; Sar *= valid; Sbr *= valid;
        float xy = x*y;
        float Jx[6], Jy[6];
        Jx[0] = -xy*fx;          Jx[1] = (1.0f + x*x)*fx; Jx[2] = -y*fx;
        Jx[3] = d*fx;            Jx[4] = 0.0f;            Jx[5] = -d*x*fx;
        Jy[0] = -(1.0f+y*y)*fy;  Jy[1] = xy*fy;           Jy[2] = x*fy;
        Jy[3] = 0.0f;            Jy[4] = d*fy;            Jy[5] = -d*y*fy;
        int idx = 0;
#pragma unroll
        for (int k = 0; k < 6; k++) {
#pragma unroll
            for (int l = k; l < 6; l++) {
                acc[idx++] = Saa*Jx[k]*Jx[l] + Sab*(Jx[k]*Jy[l] + Jy[k]*Jx[l]) + Sbb*Jy[k]*Jy[l];
            }
        }
#pragma unroll
        for (int k = 0; k < 6; k++) acc[21+k] = Sar*Jx[k] + Sbr*Jy[k];
    }

    // ---- block reduction of 27 values, then per-block atomicAdd ----
#pragma unroll
    for (int k = 0; k < 27; k++) {
#pragma unroll
        for (int off = 16; off > 0; off >>= 1)
            acc[k] += __shfl_down_sync(0xFFFFFFFFu, acc[k], off);
    }
    __shared__ float sm[27][8];
    int lane = threadIdx.x & 31;
    int warp = threadIdx.x >> 5;
    if (lane == 0) {
#pragma unroll
        for (int k = 0; k < 27; k++) sm[k][warp] = acc[k];
    }
    __syncthreads();
    if (threadIdx.x < 27) {
        float s = 0.0f;
#pragma unroll
        for (int w = 0; w < 8; w++) s += sm[threadIdx.x][w];
        atomicAdd(&g_acc[blockIdx.y][threadIdx.x], s);
        __threadfence();
    }
    __syncthreads();

    // ---- last-block-does-solve (threadFenceReduction pattern) ----
    __shared__ bool sLast;
    if (threadIdx.x == 0) {
        unsigned int done = atomicAdd(&g_count, 1u);
        sLast = (done == ITER_BLOCKS - 1);
    }
    __syncthreads();
    if (!sLast) return;
    if (threadIdx.x == 0) g_count = 0;
    __threadfence();

    if (threadIdx.x < BB) {
        int bb = threadIdx.x;
        float M[6][7];
        {
            float Jt[6][6];
            int idx = 0;
#pragma unroll
            for (int k = 0; k < 6; k++)
#pragma unroll
                for (int l = k; l < 6; l++) {
                    float vv = g_acc[bb][idx++];
                    Jt[k][l] = vv; Jt[l][k] = vv;
                }
            float tr = 0.0f;
#pragma unroll
            for (int k = 0; k < 6; k++) tr += Jt[k][k];
            float lam = tr * 1e-6f;
#pragma unroll
            for (int i = 0; i < 6; i++) {
#pragma unroll
                for (int j = 0; j < 6; j++) M[i][j] = Jt[i][j] + (i == j ? lam : 0.0f);
                M[i][6] = g_acc[bb][21+i];
            }
        }
        for (int k = 0; k < 6; k++) {
            int piv = k; float mx = fabsf(M[k][k]);
            for (int i = k+1; i < 6; i++) {
                float a = fabsf(M[i][k]);
                if (a > mx) { mx = a; piv = i; }
            }
            if (piv != k)
                for (int j = k; j < 7; j++) { float tmp = M[k][j]; M[k][j] = M[piv][j]; M[piv][j] = tmp; }
            float inv = 1.0f / M[k][k];
            for (int i = k+1; i < 6; i++) {
                float f = M[i][k] * inv;
                for (int j = k; j < 7; j++) M[i][j] -= f * M[k][j];
            }
        }
        float xi[6];
        for (int i = 5; i >= 0; i--) {
            float s = M[i][6];
            for (int j = i+1; j < 6; j++) s -= M[i][j] * xi[j];
            xi[i] = s / M[i][i];
        }

        float dR[9];
        rodrigues(-xi[0], -xi[1], -xi[2], dR);
        float dt[3];
        dt[0] = -(dR[0]*xi[3] + dR[1]*xi[4] + dR[2]*xi[5]);
        dt[1] = -(dR[3]*xi[3] + dR[4]*xi[4] + dR[5]*xi[5]);
        dt[2] = -(dR[6]*xi[3] + dR[7]*xi[4] + dR[8]*xi[5]);

        float Rb[9], tb[3];
#pragma unroll
        for (int i = 0; i < 9; i++) Rb[i] = g_R[bb][i];
#pragma unroll
        for (int i = 0; i < 3; i++) tb[i] = g_t[bb][i];

        float nt[3], nR[9];
#pragma unroll
        for (int i = 0; i < 3; i++)
            nt[i] = Rb[i*3+0]*dt[0] + Rb[i*3+1]*dt[1] + Rb[i*3+2]*dt[2] + tb[i];
#pragma unroll
        for (int i = 0; i < 3; i++)
#pragma unroll
            for (int j = 0; j < 3; j++)
                nR[i*3+j] = Rb[i*3+0]*dR[0*3+j] + Rb[i*3+1]*dR[1*3+j] + Rb[i*3+2]*dR[2*3+j];

#pragma unroll
        for (int i = 0; i < 9; i++) g_R[bb][i] = nR[i];
#pragma unroll
        for (int i = 0; i < 3; i++) g_t[bb][i] = nt[i];
#pragma unroll
        for (int k = 0; k < 27; k++) g_acc[bb][k] = 0.0f;

        if (last) {
#pragma unroll
            for (int i = 0; i < 9; i++) out[bb*12 + i] = nR[i];
#pragma unroll
            for (int i = 0; i < 3; i++) out[bb*12 + 9 + i] = nt[i];
        }
    }
}

// ---------------- launch ----------------
extern "C" void kernel_launch(void* const* d_in, const int* in_sizes, int n_in,
                              void* d_out, int out_size) {
    const float* twist0 = (const float*)d_in[0];
    const float* x0     = (const float*)d_in[1];
    const float* x1     = (const float*)d_in[2];
    const float* invD0  = (const float*)d_in[3];
    const float* invD1  = (const float*)d_in[4];
    const float* sigma0 = (const float*)d_in[5];
    const float* sigma1 = (const float*)d_in[6];
    const float* Kmat   = (const float*)d_in[7];
    float* out = (float*)d_out;

    packKernel<<<BB*PAIRS*NN/256, 256>>>(twist0, x0, sigma0, x1, sigma1);
    for (int it = 0; it < 3; ++it) {
        dim3 grid(NN/256, BB);
        iterKernel<<<grid, 256>>>(invD0, invD1, Kmat, out, it == 2);
    }
}